// round 12
// baseline (speedup 1.0000x reference)
#include <cuda_runtime.h>
#include <math.h>

#define NB 128
#define LXD 512
#define DD 32
#define KK 63
#define FF 2016   // KK*DD

// W3 pre-tiled and pre-scaled by log2(e): g_W3S[r][jj][fl], jj=63 row = b3.
// Logits come out as z*log2e -> exp2f(acc) == exp(z).
__device__ float g_W3S[32 * 64 * 64];

__global__ void prep_w3(const float* __restrict__ W3, const float* __restrict__ b3) {
    const float LOG2E = 1.4426950408889634f;
    int idx = blockIdx.x * blockDim.x + threadIdx.x;
    if (idx >= 32 * 64 * 64) return;
    int fl = idx & 63, jj = (idx >> 6) & 63, r = idx >> 12;
    int f = r * 64 + fl;
    float v = 0.f;
    if (f < FF) v = ((jj < KK) ? W3[jj * FF + f] : b3[f]) * LOG2E;
    g_W3S[idx] = v;
}

// SMEM layout (floats) — 56384 floats = 225536 bytes
#define OFF_X    0          // Xs  [512][32] = 16384 (compacted rows)
#define OFF_H    16384      // Hst [64][516] = 33024 (row 63 = ones)
#define OFF_W    49408      // Wt  [64][68]  = 4352
#define OFF_R1   53760      // [16][64]
#define OFF_R2   54784      // [16][64]
#define OFF_OS   55808      // 64
#define OFF_PERM 55872      // 512 (ints)
#define SMEM_FLOATS 56384

__global__ __launch_bounds__(512, 1)
void ttcn_main(const float* __restrict__ Xg, const float* __restrict__ Mg,
               const float* __restrict__ W1g, const float* __restrict__ b1g,
               const float* __restrict__ W2g, const float* __restrict__ b2g,
               const float* __restrict__ Tb,  float* __restrict__ Og)
{
    extern __shared__ float sm[];
    float* Xs = sm + OFF_X;
    float* Hs = sm + OFF_H;
    float* Ws = sm + OFF_W;
    float* R1 = sm + OFF_R1;
    float* R2 = sm + OFF_R2;
    float* OS = sm + OFF_OS;
    int*   Pm = (int*)(sm + OFF_PERM);

    const int n    = blockIdx.x;
    const int t    = threadIdx.x;
    const int g    = t & 7;       // feature sub-group: owns f_local = g*8..g*8+7
    const int lt   = t >> 3;      // slot-group (0..63): slots lt*8..lt*8+7
    const int warp = t >> 5;
    const int lane = t & 31;
    const int l0   = lt * 8;
    const int gq4  = (g & 3) * 8; // d-segment base for pooling

    // ---------- mask compaction: ballot + prefix scan over l ----------
    int m_i = (Mg[n * LXD + t] > 0.5f) ? 1 : 0;
    unsigned bal = __ballot_sync(0xffffffffu, m_i);
    if (lane == 0) ((int*)R1)[warp] = __popc(bal);
    __syncthreads();
    int base = 0, Lm = 0;
    #pragma unroll
    for (int w = 0; w < 16; w++) {
        int c = ((int*)R1)[w];
        if (w < warp) base += c;
        Lm += c;
    }
    if (m_i) Pm[base + __popc(bal & ((1u << lane) - 1u))] = t;
    __syncthreads();
    const int Lm_pad = (Lm + 7) & ~7;
    const int Ng = Lm_pad >> 3;          // active slot-groups
    const bool act = (lt < Ng);

    // ---------- stage compacted X + W1 tile + ones-row + OS ----------
    {
        const float4* X4 = (const float4*)(Xg + (size_t)n * (LXD * DD));
        float4* Xs4 = (float4*)Xs;
        for (int idx = t; idx < Ng * 64; idx += 512) {   // Lm_pad rows x 8 float4
            int s = idx >> 3, q = idx & 7;
            float4 v = make_float4(0.f, 0.f, 0.f, 0.f);
            if (s < Lm) v = X4[Pm[s] * 8 + q];
            Xs4[s * 8 + q] = v;
        }
        for (int idx = t; idx < 32 * 64; idx += 512) {
            int d = idx >> 6, j = idx & 63;
            Ws[d * 68 + j] = (j < KK) ? W1g[d * KK + j] : 0.f;
        }
        Hs[63 * 516 + t] = 1.f;      // ones row (b3 folding in Phase C)
        if (t < 64) OS[t] = 0.f;
    }
    float b1r[8], b2r[8];
    #pragma unroll
    for (int fi = 0; fi < 8; fi++) {
        int j = g * 8 + fi;
        b1r[fi] = (j < KK) ? b1g[j] : 0.f;
        b2r[fi] = (j < KK) ? b2g[j] : 0.f;
    }
    float mreg[8];
    #pragma unroll
    for (int i = 0; i < 8; i++) mreg[i] = (l0 + i < Lm) ? 1.f : 0.f;  // pad slots -> 0
    __syncthreads();

    // ---------- Phase A: H1 = relu(Xc @ W1 + b1) -> Hst rows 0..62 ----------
    {
        float acc[8][8];
        #pragma unroll
        for (int i = 0; i < 8; i++)
            #pragma unroll
            for (int fi = 0; fi < 8; fi++) acc[i][fi] = 0.f;

        if (act) {
            #pragma unroll 4
            for (int d = 0; d < 32; ++d) {
                float h[8];
                #pragma unroll
                for (int i = 0; i < 8; i++) h[i] = Xs[(l0 + i) * 32 + d];
                float4 w0 = *(const float4*)&Ws[d * 68 + g * 8];
                float4 w1 = *(const float4*)&Ws[d * 68 + g * 8 + 4];
                float w[8] = {w0.x, w0.y, w0.z, w0.w, w1.x, w1.y, w1.z, w1.w};
                #pragma unroll
                for (int i = 0; i < 8; i++)
                    #pragma unroll
                    for (int fi = 0; fi < 8; fi++) acc[i][fi] += h[i] * w[fi];
            }
        }
        __syncthreads();   // all W1 reads done before Ws overwritten

        if (act) {
            #pragma unroll
            for (int fi = 0; fi < 8; fi++) {
                int j = g * 8 + fi;
                if (j < KK) {
                    float4 v0, v1;
                    v0.x = fmaxf(acc[0][fi] + b1r[fi], 0.f);
                    v0.y = fmaxf(acc[1][fi] + b1r[fi], 0.f);
                    v0.z = fmaxf(acc[2][fi] + b1r[fi], 0.f);
                    v0.w = fmaxf(acc[3][fi] + b1r[fi], 0.f);
                    v1.x = fmaxf(acc[4][fi] + b1r[fi], 0.f);
                    v1.y = fmaxf(acc[5][fi] + b1r[fi], 0.f);
                    v1.z = fmaxf(acc[6][fi] + b1r[fi], 0.f);
                    v1.w = fmaxf(acc[7][fi] + b1r[fi], 0.f);
                    *(float4*)&Hs[j * 516 + l0]     = v0;
                    *(float4*)&Hs[j * 516 + l0 + 4] = v1;
                }
            }
        }
        for (int idx = t; idx < KK * 64; idx += 512) {
            int m = idx >> 6, col = idx & 63;
            Ws[m * 68 + col] = (col < KK) ? W2g[m * KK + col] : 0.f;
        }
    }
    __syncthreads();

    // ---------- Phase B: H2 = relu(H1 @ W2 + b2), in place ----------
    {
        float acc[8][8];
        #pragma unroll
        for (int i = 0; i < 8; i++)
            #pragma unroll
            for (int fi = 0; fi < 8; fi++) acc[i][fi] = 0.f;

        if (act) {
            #pragma unroll 7
            for (int m = 0; m < KK; ++m) {
                float4 a0 = *(const float4*)&Hs[m * 516 + l0];
                float4 a1 = *(const float4*)&Hs[m * 516 + l0 + 4];
                float4 w0 = *(const float4*)&Ws[m * 68 + g * 8];
                float4 w1 = *(const float4*)&Ws[m * 68 + g * 8 + 4];
                float h[8] = {a0.x, a0.y, a0.z, a0.w, a1.x, a1.y, a1.z, a1.w};
                float w[8] = {w0.x, w0.y, w0.z, w0.w, w1.x, w1.y, w1.z, w1.w};
                #pragma unroll
                for (int i = 0; i < 8; i++)
                    #pragma unroll
                    for (int fi = 0; fi < 8; fi++) acc[i][fi] += h[i] * w[fi];
            }
        }
        __syncwarp();   // all lanes participate; orders reads before in-place writes
        if (act) {
            #pragma unroll
            for (int fi = 0; fi < 8; fi++) {
                int j = g * 8 + fi;
                if (j < KK) {
                    float4 v0, v1;
                    v0.x = fmaxf(acc[0][fi] + b2r[fi], 0.f);
                    v0.y = fmaxf(acc[1][fi] + b2r[fi], 0.f);
                    v0.z = fmaxf(acc[2][fi] + b2r[fi], 0.f);
                    v0.w = fmaxf(acc[3][fi] + b2r[fi], 0.f);
                    v1.x = fmaxf(acc[4][fi] + b2r[fi], 0.f);
                    v1.y = fmaxf(acc[5][fi] + b2r[fi], 0.f);
                    v1.z = fmaxf(acc[6][fi] + b2r[fi], 0.f);
                    v1.w = fmaxf(acc[7][fi] + b2r[fi], 0.f);
                    *(float4*)&Hs[j * 516 + l0]     = v0;
                    *(float4*)&Hs[j * 516 + l0 + 4] = v1;
                }
            }
        }
    }
    __syncthreads();   // W2 reads done before Phase C restages Ws

    // ---------- Phase C: logits GEMM (b3+log2e folded) + exp2 softmax + pooling ----------
    for (int r = 0; r < 32; ++r) {
        {
            const float4* src = (const float4*)(g_W3S + r * 4096);
            #pragma unroll 2
            for (int idx = t; idx < 1024; idx += 512) {
                int jj = idx >> 4, q = idx & 15;
                *(float4*)&Ws[jj * 68 + q * 4] = src[idx];
            }
        }
        __syncthreads();

        float Sp[8], Ap[8];
        #pragma unroll
        for (int fi = 0; fi < 8; fi++) { Sp[fi] = 0.f; Ap[fi] = 0.f; }

        if (act) {
            float acc[8][8];
            #pragma unroll
            for (int i = 0; i < 8; i++)
                #pragma unroll
                for (int fi = 0; fi < 8; fi++) acc[i][fi] = 0.f;

            #pragma unroll 8
            for (int j = 0; j < 64; ++j) {      // j=63 ones-row adds b3*log2e
                float4 a0 = *(const float4*)&Hs[j * 516 + l0];
                float4 a1 = *(const float4*)&Hs[j * 516 + l0 + 4];
                float4 w0 = *(const float4*)&Ws[j * 68 + g * 8];
                float4 w1 = *(const float4*)&Ws[j * 68 + g * 8 + 4];
                float h[8] = {a0.x, a0.y, a0.z, a0.w, a1.x, a1.y, a1.z, a1.w};
                float w[8] = {w0.x, w0.y, w0.z, w0.w, w1.x, w1.y, w1.z, w1.w};
                #pragma unroll
                for (int i = 0; i < 8; i++)
                    #pragma unroll
                    for (int fi = 0; fi < 8; fi++) acc[i][fi] += h[i] * w[fi];
            }

            // exp2 (logits pre-scaled by log2e) + pad-mask + S/A partials
            #pragma unroll
            for (int i = 0; i < 8; i++) {
                float4 x0 = *(const float4*)&Xs[(l0 + i) * 32 + gq4];
                float4 x1 = *(const float4*)&Xs[(l0 + i) * 32 + gq4 + 4];
                float x8[8] = {x0.x, x0.y, x0.z, x0.w, x1.x, x1.y, x1.z, x1.w};
                float mi = mreg[i];
                #pragma unroll
                for (int fi = 0; fi < 8; fi++) {
                    float e = exp2f(acc[i][fi]) * mi;
                    Sp[fi] += e;
                    Ap[fi] += e * x8[fi];        // d = 8*(g&3) + fi
                }
            }
        }
        #pragma unroll
        for (int fi = 0; fi < 8; fi++) {
            Sp[fi] += __shfl_xor_sync(0xffffffffu, Sp[fi], 8);
            Sp[fi] += __shfl_xor_sync(0xffffffffu, Sp[fi], 16);
            Ap[fi] += __shfl_xor_sync(0xffffffffu, Ap[fi], 8);
            Ap[fi] += __shfl_xor_sync(0xffffffffu, Ap[fi], 16);
        }
        if (lane < 8) {
            float4 s0 = {Sp[0], Sp[1], Sp[2], Sp[3]};
            float4 s1 = {Sp[4], Sp[5], Sp[6], Sp[7]};
            float4 a0 = {Ap[0], Ap[1], Ap[2], Ap[3]};
            float4 a1 = {Ap[4], Ap[5], Ap[6], Ap[7]};
            *(float4*)&R1[warp * 64 + lane * 8]     = s0;
            *(float4*)&R1[warp * 64 + lane * 8 + 4] = s1;
            *(float4*)&R2[warp * 64 + lane * 8]     = a0;
            *(float4*)&R2[warp * 64 + lane * 8 + 4] = a1;
        }
        __syncthreads();
        if (t < 64) {
            float S = 0.f, A = 0.f;
            #pragma unroll
            for (int w16 = 0; w16 < 16; w16++) {
                S += R1[w16 * 64 + t];
                A += R2[w16 * 64 + t];
            }
            int f = r * 64 + t;
            float gq = (f < FF) ? (A / S) : 0.f;
            gq += __shfl_down_sync(0xffffffffu, gq, 16);
            gq += __shfl_down_sync(0xffffffffu, gq, 8);
            gq += __shfl_down_sync(0xffffffffu, gq, 4);
            gq += __shfl_down_sync(0xffffffffu, gq, 2);
            gq += __shfl_down_sync(0xffffffffu, gq, 1);
            if (lane == 0) OS[2 * r + warp] = gq;   // k = 2r + warp
        }
        // next round's stage-sync orders Ws restage vs R reads
    }
    __syncthreads();

    if (t < KK) Og[n * KK + t] = fmaxf(OS[t] + Tb[t], 0.f);
}

extern "C" void kernel_launch(void* const* d_in, const int* in_sizes, int n_in,
                              void* d_out, int out_size) {
    const float* X  = (const float*)d_in[0];
    const float* M  = (const float*)d_in[1];
    const float* W1 = (const float*)d_in[2];
    const float* b1 = (const float*)d_in[3];
    const float* W2 = (const float*)d_in[4];
    const float* b2 = (const float*)d_in[5];
    const float* W3 = (const float*)d_in[6];
    const float* b3 = (const float*)d_in[7];
    const float* Tb = (const float*)d_in[8];
    float* Og = (float*)d_out;

    prep_w3<<<(32 * 64 * 64 + 255) / 256, 256>>>(W3, b3);

    size_t smem = (size_t)SMEM_FLOATS * sizeof(float);
    cudaFuncSetAttribute(ttcn_main, cudaFuncAttributeMaxDynamicSharedMemorySize, (int)smem);
    ttcn_main<<<NB, 512, smem>>>(X, M, W1, b1, W2, b2, Tb, Og);
}

// round 13
// speedup vs baseline: 1.0651x; 1.0651x over previous
#include <cuda_runtime.h>
#include <math.h>

#define NB 128
#define LXD 512
#define DD 32
#define KK 63
#define FF 2016   // KK*DD

// W3 pre-tiled and pre-scaled by log2(e): g_W3S[r][jj][fl], jj=63 row = b3.
// Logits come out as z*log2e -> exp2f(acc) == exp(z).
__device__ float g_W3S[32 * 64 * 64];

__global__ void prep_w3(const float* __restrict__ W3, const float* __restrict__ b3) {
    const float LOG2E = 1.4426950408889634f;
    int idx = blockIdx.x * blockDim.x + threadIdx.x;
    if (idx >= 32 * 64 * 64) return;
    int fl = idx & 63, jj = (idx >> 6) & 63, r = idx >> 12;
    int f = r * 64 + fl;
    float v = 0.f;
    if (f < FF) v = ((jj < KK) ? W3[jj * FF + f] : b3[f]) * LOG2E;
    g_W3S[idx] = v;
}

// SMEM layout (floats) — 56384 floats = 225536 bytes
#define OFF_X    0          // Xs  [512][32] = 16384 (compacted rows)
#define OFF_H    16384      // Hst [64][516] = 33024 (row 63 = ones)
#define OFF_W    49408      // Wt  [64][68]  = 4352
#define OFF_R1   53760      // [16][64]
#define OFF_R2   54784      // [16][64]
#define OFF_OS   55808      // 64
#define OFF_PERM 55872      // 512 (ints)
#define SMEM_FLOATS 56384

// One Phase-C pass over 4 compacted rows starting at `base`:
// 4x8 logits tile (b3 folded via ones-row), exp2, pad-masked S/A partials.
__device__ __forceinline__ void phaseC_pass(
    const float* __restrict__ Hs, const float* __restrict__ Ws,
    const float* __restrict__ Xs, int base, int Lm, int g, int gq4,
    float Sp[8], float Ap[8])
{
    float acc[4][8];
    #pragma unroll
    for (int i = 0; i < 4; i++)
        #pragma unroll
        for (int fi = 0; fi < 8; fi++) acc[i][fi] = 0.f;

    #pragma unroll 8
    for (int j = 0; j < 64; ++j) {          // j=63 is the ones-row -> adds b3*log2e
        float4 a0 = *(const float4*)&Hs[j * 516 + base];
        float4 w0 = *(const float4*)&Ws[j * 68 + g * 8];
        float4 w1 = *(const float4*)&Ws[j * 68 + g * 8 + 4];
        float h[4] = {a0.x, a0.y, a0.z, a0.w};
        float w[8] = {w0.x, w0.y, w0.z, w0.w, w1.x, w1.y, w1.z, w1.w};
        #pragma unroll
        for (int i = 0; i < 4; i++)
            #pragma unroll
            for (int fi = 0; fi < 8; fi++) acc[i][fi] += h[i] * w[fi];
    }
    #pragma unroll
    for (int i = 0; i < 4; i++) {
        float mi = (base + i < Lm) ? 1.f : 0.f;    // pad rows contribute exactly 0
        float4 x0 = *(const float4*)&Xs[(base + i) * 32 + gq4];
        float4 x1 = *(const float4*)&Xs[(base + i) * 32 + gq4 + 4];
        float x8[8] = {x0.x, x0.y, x0.z, x0.w, x1.x, x1.y, x1.z, x1.w};
        #pragma unroll
        for (int fi = 0; fi < 8; fi++) {
            float e = exp2f(acc[i][fi]) * mi;
            Sp[fi] += e;
            Ap[fi] += e * x8[fi];                 // d = 8*(g&3) + fi
        }
    }
}

__global__ __launch_bounds__(512, 1)
void ttcn_main(const float* __restrict__ Xg, const float* __restrict__ Mg,
               const float* __restrict__ W1g, const float* __restrict__ b1g,
               const float* __restrict__ W2g, const float* __restrict__ b2g,
               const float* __restrict__ Tb,  float* __restrict__ Og)
{
    extern __shared__ float sm[];
    float* Xs = sm + OFF_X;
    float* Hs = sm + OFF_H;
    float* Ws = sm + OFF_W;
    float* R1 = sm + OFF_R1;
    float* R2 = sm + OFF_R2;
    float* OS = sm + OFF_OS;
    int*   Pm = (int*)(sm + OFF_PERM);

    const int n    = blockIdx.x;
    const int t    = threadIdx.x;
    const int g    = t & 7;       // feature sub-group: owns f_local = g*8..g*8+7
    const int lt   = t >> 3;      // slot-group (0..63)
    const int warp = t >> 5;
    const int lane = t & 31;
    const int l08  = lt * 8;      // Phase A/B row base (8-row tiles)
    const int gq4  = (g & 3) * 8; // d-segment base for pooling

    // ---------- mask compaction: ballot + prefix scan over l ----------
    int m_i = (Mg[n * LXD + t] > 0.5f) ? 1 : 0;
    unsigned bal = __ballot_sync(0xffffffffu, m_i);
    if (lane == 0) ((int*)R1)[warp] = __popc(bal);
    __syncthreads();
    int base = 0, Lm = 0;
    #pragma unroll
    for (int w = 0; w < 16; w++) {
        int c = ((int*)R1)[w];
        if (w < warp) base += c;
        Lm += c;
    }
    if (m_i) Pm[base + __popc(bal & ((1u << lane) - 1u))] = t;
    __syncthreads();
    const int Lm_pad4 = (Lm + 3) & ~3;
    const int Lm_pad8 = (Lm + 7) & ~7;
    const int R0cap   = (Lm_pad4 < 256) ? Lm_pad4 : 256;   // pass-0 row cap
    const bool tail   = (Lm_pad4 > 256);                   // pass-1 exists (CTA-uniform)
    const bool act8   = (l08 < Lm_pad8);                   // Phase A/B activity

    // ---------- stage compacted X (zero pad to Lm_pad8) + W1 + ones-row + OS ----------
    {
        const float4* X4 = (const float4*)(Xg + (size_t)n * (LXD * DD));
        float4* Xs4 = (float4*)Xs;
        for (int idx = t; idx < Lm_pad8 * 8; idx += 512) {
            int s = idx >> 3, q = idx & 7;
            float4 v = make_float4(0.f, 0.f, 0.f, 0.f);
            if (s < Lm) v = X4[Pm[s] * 8 + q];
            Xs4[s * 8 + q] = v;
        }
        for (int idx = t; idx < 32 * 64; idx += 512) {
            int d = idx >> 6, j = idx & 63;
            Ws[d * 68 + j] = (j < KK) ? W1g[d * KK + j] : 0.f;
        }
        Hs[63 * 516 + t] = 1.f;      // ones row (b3 folding in Phase C)
        if (t < 64) OS[t] = 0.f;
    }
    float b1r[8], b2r[8];
    #pragma unroll
    for (int fi = 0; fi < 8; fi++) {
        int j = g * 8 + fi;
        b1r[fi] = (j < KK) ? b1g[j] : 0.f;
        b2r[fi] = (j < KK) ? b2g[j] : 0.f;
    }
    __syncthreads();

    // ---------- Phase A: H1 = relu(Xc @ W1 + b1) -> Hst rows 0..62 ----------
    {
        float acc[8][8];
        #pragma unroll
        for (int i = 0; i < 8; i++)
            #pragma unroll
            for (int fi = 0; fi < 8; fi++) acc[i][fi] = 0.f;

        if (act8) {
            #pragma unroll 4
            for (int d = 0; d < 32; ++d) {
                float h[8];
                #pragma unroll
                for (int i = 0; i < 8; i++) h[i] = Xs[(l08 + i) * 32 + d];
                float4 w0 = *(const float4*)&Ws[d * 68 + g * 8];
                float4 w1 = *(const float4*)&Ws[d * 68 + g * 8 + 4];
                float w[8] = {w0.x, w0.y, w0.z, w0.w, w1.x, w1.y, w1.z, w1.w};
                #pragma unroll
                for (int i = 0; i < 8; i++)
                    #pragma unroll
                    for (int fi = 0; fi < 8; fi++) acc[i][fi] += h[i] * w[fi];
            }
        }
        __syncthreads();   // all W1 reads done before Ws overwritten

        if (act8) {
            #pragma unroll
            for (int fi = 0; fi < 8; fi++) {
                int j = g * 8 + fi;
                if (j < KK) {
                    float4 v0, v1;
                    v0.x = fmaxf(acc[0][fi] + b1r[fi], 0.f);
                    v0.y = fmaxf(acc[1][fi] + b1r[fi], 0.f);
                    v0.z = fmaxf(acc[2][fi] + b1r[fi], 0.f);
                    v0.w = fmaxf(acc[3][fi] + b1r[fi], 0.f);
                    v1.x = fmaxf(acc[4][fi] + b1r[fi], 0.f);
                    v1.y = fmaxf(acc[5][fi] + b1r[fi], 0.f);
                    v1.z = fmaxf(acc[6][fi] + b1r[fi], 0.f);
                    v1.w = fmaxf(acc[7][fi] + b1r[fi], 0.f);
                    *(float4*)&Hs[j * 516 + l08]     = v0;
                    *(float4*)&Hs[j * 516 + l08 + 4] = v1;
                }
            }
        }
        for (int idx = t; idx < KK * 64; idx += 512) {
            int m = idx >> 6, col = idx & 63;
            Ws[m * 68 + col] = (col < KK) ? W2g[m * KK + col] : 0.f;
        }
    }
    __syncthreads();

    // ---------- Phase B: H2 = relu(H1 @ W2 + b2), in place ----------
    {
        float acc[8][8];
        #pragma unroll
        for (int i = 0; i < 8; i++)
            #pragma unroll
            for (int fi = 0; fi < 8; fi++) acc[i][fi] = 0.f;

        if (act8) {
            #pragma unroll 7
            for (int m = 0; m < KK; ++m) {
                float4 a0 = *(const float4*)&Hs[m * 516 + l08];
                float4 a1 = *(const float4*)&Hs[m * 516 + l08 + 4];
                float4 w0 = *(const float4*)&Ws[m * 68 + g * 8];
                float4 w1 = *(const float4*)&Ws[m * 68 + g * 8 + 4];
                float h[8] = {a0.x, a0.y, a0.z, a0.w, a1.x, a1.y, a1.z, a1.w};
                float w[8] = {w0.x, w0.y, w0.z, w0.w, w1.x, w1.y, w1.z, w1.w};
                #pragma unroll
                for (int i = 0; i < 8; i++)
                    #pragma unroll
                    for (int fi = 0; fi < 8; fi++) acc[i][fi] += h[i] * w[fi];
            }
        }
        __syncwarp();   // readers==writers of these H columns are this warp's 8-thread groups
        if (act8) {
            #pragma unroll
            for (int fi = 0; fi < 8; fi++) {
                int j = g * 8 + fi;
                if (j < KK) {
                    float4 v0, v1;
                    v0.x = fmaxf(acc[0][fi] + b2r[fi], 0.f);
                    v0.y = fmaxf(acc[1][fi] + b2r[fi], 0.f);
                    v0.z = fmaxf(acc[2][fi] + b2r[fi], 0.f);
                    v0.w = fmaxf(acc[3][fi] + b2r[fi], 0.f);
                    v1.x = fmaxf(acc[4][fi] + b2r[fi], 0.f);
                    v1.y = fmaxf(acc[5][fi] + b2r[fi], 0.f);
                    v1.z = fmaxf(acc[6][fi] + b2r[fi], 0.f);
                    v1.w = fmaxf(acc[7][fi] + b2r[fi], 0.f);
                    *(float4*)&Hs[j * 516 + l08]     = v0;
                    *(float4*)&Hs[j * 516 + l08 + 4] = v1;
                }
            }
        }
    }
    __syncthreads();   // W2 reads done before Phase C restages Ws

    // ---------- Phase C: 4-row tiles, pass 0 = rows 0..255, pass 1 = rows 256+ ----------
    const int base0 = lt * 4;
    // pass-1 group->block bijection spreads the few active groups across warps/SMSPs
    const int base1 = 256 + ((((lt & 3) << 4) | (lt >> 2)) << 2);

    for (int r = 0; r < 32; ++r) {
        {
            const float4* src = (const float4*)(g_W3S + r * 4096);
            #pragma unroll 2
            for (int idx = t; idx < 1024; idx += 512) {
                int jj = idx >> 4, q = idx & 15;
                *(float4*)&Ws[jj * 68 + q * 4] = src[idx];
            }
        }
        __syncthreads();

        float Sp[8], Ap[8];
        #pragma unroll
        for (int fi = 0; fi < 8; fi++) { Sp[fi] = 0.f; Ap[fi] = 0.f; }

        if (base0 < R0cap)
            phaseC_pass(Hs, Ws, Xs, base0, Lm, g, gq4, Sp, Ap);
        if (tail) {
            if (base1 < Lm_pad4)
                phaseC_pass(Hs, Ws, Xs, base1, Lm, g, gq4, Sp, Ap);
        }

        #pragma unroll
        for (int fi = 0; fi < 8; fi++) {
            Sp[fi] += __shfl_xor_sync(0xffffffffu, Sp[fi], 8);
            Sp[fi] += __shfl_xor_sync(0xffffffffu, Sp[fi], 16);
            Ap[fi] += __shfl_xor_sync(0xffffffffu, Ap[fi], 8);
            Ap[fi] += __shfl_xor_sync(0xffffffffu, Ap[fi], 16);
        }
        if (lane < 8) {
            float4 s0 = {Sp[0], Sp[1], Sp[2], Sp[3]};
            float4 s1 = {Sp[4], Sp[5], Sp[6], Sp[7]};
            float4 a0 = {Ap[0], Ap[1], Ap[2], Ap[3]};
            float4 a1 = {Ap[4], Ap[5], Ap[6], Ap[7]};
            *(float4*)&R1[warp * 64 + lane * 8]     = s0;
            *(float4*)&R1[warp * 64 + lane * 8 + 4] = s1;
            *(float4*)&R2[warp * 64 + lane * 8]     = a0;
            *(float4*)&R2[warp * 64 + lane * 8 + 4] = a1;
        }
        __syncthreads();
        if (t < 64) {
            float S = 0.f, A = 0.f;
            #pragma unroll
            for (int w16 = 0; w16 < 16; w16++) {
                S += R1[w16 * 64 + t];
                A += R2[w16 * 64 + t];
            }
            int f = r * 64 + t;
            float gq = (f < FF) ? (A / S) : 0.f;
            gq += __shfl_down_sync(0xffffffffu, gq, 16);
            gq += __shfl_down_sync(0xffffffffu, gq, 8);
            gq += __shfl_down_sync(0xffffffffu, gq, 4);
            gq += __shfl_down_sync(0xffffffffu, gq, 2);
            gq += __shfl_down_sync(0xffffffffu, gq, 1);
            if (lane == 0) OS[2 * r + warp] = gq;   // k = 2r + warp
        }
        // next round's stage-sync orders Ws restage vs R reads
    }
    __syncthreads();

    if (t < KK) Og[n * KK + t] = fmaxf(OS[t] + Tb[t], 0.f);
}

extern "C" void kernel_launch(void* const* d_in, const int* in_sizes, int n_in,
                              void* d_out, int out_size) {
    const float* X  = (const float*)d_in[0];
    const float* M  = (const float*)d_in[1];
    const float* W1 = (const float*)d_in[2];
    const float* b1 = (const float*)d_in[3];
    const float* W2 = (const float*)d_in[4];
    const float* b2 = (const float*)d_in[5];
    const float* W3 = (const float*)d_in[6];
    const float* b3 = (const float*)d_in[7];
    const float* Tb = (const float*)d_in[8];
    float* Og = (float*)d_out;

    prep_w3<<<(32 * 64 * 64 + 255) / 256, 256>>>(W3, b3);

    size_t smem = (size_t)SMEM_FLOATS * sizeof(float);
    cudaFuncSetAttribute(ttcn_main, cudaFuncAttributeMaxDynamicSharedMemorySize, (int)smem);
    ttcn_main<<<NB, 512, smem>>>(X, M, W1, b1, W2, b2, Tb, Og);
}

// round 14
// speedup vs baseline: 1.3695x; 1.2858x over previous
#include <cuda_runtime.h>
#include <math.h>

#define NB 128
#define LXD 512
#define DD 32
#define KK 63
#define FF 2016   // KK*DD

// W3 pre-tiled and pre-scaled by log2(e): g_W3S[r][jj][fl], jj=63 row = b3.
// Logits come out as z*log2e -> exp2f(acc) == exp(z).
__device__ float g_W3S[32 * 64 * 64];

__global__ void prep_w3(const float* __restrict__ W3, const float* __restrict__ b3) {
    const float LOG2E = 1.4426950408889634f;
    int idx = blockIdx.x * blockDim.x + threadIdx.x;
    if (idx >= 32 * 64 * 64) return;
    int fl = idx & 63, jj = (idx >> 6) & 63, r = idx >> 12;
    int f = r * 64 + fl;
    float v = 0.f;
    if (f < FF) v = ((jj < KK) ? W3[jj * FF + f] : b3[f]) * LOG2E;
    g_W3S[idx] = v;
}

// SMEM layout (floats) — 56384 floats = 225536 bytes
#define OFF_X    0          // Xs  [512][32] = 16384 (compacted rows)
#define OFF_H    16384      // Hst [64][516] = 33024 (row 63 = ones)
#define OFF_W    49408      // Wt  [64][68]  = 4352
#define OFF_R1   53760      // [16][64]
#define OFF_R2   54784      // [16][64]
#define OFF_OS   55808      // 64
#define OFF_PERM 55872      // 512 (ints)
#define SMEM_FLOATS 56384

__global__ __launch_bounds__(512, 1)
void ttcn_main(const float* __restrict__ Xg, const float* __restrict__ Mg,
               const float* __restrict__ W1g, const float* __restrict__ b1g,
               const float* __restrict__ W2g, const float* __restrict__ b2g,
               const float* __restrict__ Tb,  float* __restrict__ Og)
{
    extern __shared__ float sm[];
    float* Xs = sm + OFF_X;
    float* Hs = sm + OFF_H;
    float* Ws = sm + OFF_W;
    float* R1 = sm + OFF_R1;
    float* R2 = sm + OFF_R2;
    float* OS = sm + OFF_OS;
    int*   Pm = (int*)(sm + OFF_PERM);

    const int n    = blockIdx.x;
    const int t    = threadIdx.x;
    const int g    = t & 7;       // feature sub-group: owns f_local = g*8..g*8+7
    const int lt   = t >> 3;      // slot-group (0..63)
    const int warp = t >> 5;
    const int lane = t & 31;
    const int l08  = lt * 8;      // Phase A/B row base (8-row tiles)
    const int gq4  = (g & 3) * 8; // d-segment base for pooling

    // ---------- mask compaction: ballot + prefix scan over l ----------
    int m_i = (Mg[n * LXD + t] > 0.5f) ? 1 : 0;
    unsigned bal = __ballot_sync(0xffffffffu, m_i);
    if (lane == 0) ((int*)R1)[warp] = __popc(bal);
    __syncthreads();
    int base = 0, Lm = 0;
    #pragma unroll
    for (int w = 0; w < 16; w++) {
        int c = ((int*)R1)[w];
        if (w < warp) base += c;
        Lm += c;
    }
    if (m_i) Pm[base + __popc(bal & ((1u << lane) - 1u))] = t;
    __syncthreads();
    const int Lm_pad8 = (Lm + 7) & ~7;
    const bool act8   = (l08 < Lm_pad8);                   // Phase A/B activity

    // ---------- stage compacted X (zero pad to Lm_pad8) + W1 + ones-row + OS ----------
    {
        const float4* X4 = (const float4*)(Xg + (size_t)n * (LXD * DD));
        float4* Xs4 = (float4*)Xs;
        for (int idx = t; idx < Lm_pad8 * 8; idx += 512) {
            int s = idx >> 3, q = idx & 7;
            float4 v = make_float4(0.f, 0.f, 0.f, 0.f);
            if (s < Lm) v = X4[Pm[s] * 8 + q];
            Xs4[s * 8 + q] = v;
        }
        for (int idx = t; idx < 32 * 64; idx += 512) {
            int d = idx >> 6, j = idx & 63;
            Ws[d * 68 + j] = (j < KK) ? W1g[d * KK + j] : 0.f;
        }
        Hs[63 * 516 + t] = 1.f;      // ones row (b3 folding in Phase C)
        if (t < 64) OS[t] = 0.f;
    }
    float b1r[8], b2r[8];
    #pragma unroll
    for (int fi = 0; fi < 8; fi++) {
        int j = g * 8 + fi;
        b1r[fi] = (j < KK) ? b1g[j] : 0.f;
        b2r[fi] = (j < KK) ? b2g[j] : 0.f;
    }
    __syncthreads();

    // ---------- Phase A: H1 = relu(Xc @ W1 + b1) -> Hst rows 0..62 ----------
    {
        float acc[8][8];
        #pragma unroll
        for (int i = 0; i < 8; i++)
            #pragma unroll
            for (int fi = 0; fi < 8; fi++) acc[i][fi] = 0.f;

        if (act8) {
            #pragma unroll 4
            for (int d = 0; d < 32; ++d) {
                float h[8];
                #pragma unroll
                for (int i = 0; i < 8; i++) h[i] = Xs[(l08 + i) * 32 + d];
                float4 w0 = *(const float4*)&Ws[d * 68 + g * 8];
                float4 w1 = *(const float4*)&Ws[d * 68 + g * 8 + 4];
                float w[8] = {w0.x, w0.y, w0.z, w0.w, w1.x, w1.y, w1.z, w1.w};
                #pragma unroll
                for (int i = 0; i < 8; i++)
                    #pragma unroll
                    for (int fi = 0; fi < 8; fi++) acc[i][fi] += h[i] * w[fi];
            }
        }
        __syncthreads();   // all W1 reads done before Ws overwritten

        if (act8) {
            #pragma unroll
            for (int fi = 0; fi < 8; fi++) {
                int j = g * 8 + fi;
                if (j < KK) {
                    float4 v0, v1;
                    v0.x = fmaxf(acc[0][fi] + b1r[fi], 0.f);
                    v0.y = fmaxf(acc[1][fi] + b1r[fi], 0.f);
                    v0.z = fmaxf(acc[2][fi] + b1r[fi], 0.f);
                    v0.w = fmaxf(acc[3][fi] + b1r[fi], 0.f);
                    v1.x = fmaxf(acc[4][fi] + b1r[fi], 0.f);
                    v1.y = fmaxf(acc[5][fi] + b1r[fi], 0.f);
                    v1.z = fmaxf(acc[6][fi] + b1r[fi], 0.f);
                    v1.w = fmaxf(acc[7][fi] + b1r[fi], 0.f);
                    *(float4*)&Hs[j * 516 + l08]     = v0;
                    *(float4*)&Hs[j * 516 + l08 + 4] = v1;
                }
            }
        }
        for (int idx = t; idx < KK * 64; idx += 512) {
            int m = idx >> 6, col = idx & 63;
            Ws[m * 68 + col] = (col < KK) ? W2g[m * KK + col] : 0.f;
        }
    }
    __syncthreads();

    // ---------- Phase B: H2 = relu(H1 @ W2 + b2), in place ----------
    {
        float acc[8][8];
        #pragma unroll
        for (int i = 0; i < 8; i++)
            #pragma unroll
            for (int fi = 0; fi < 8; fi++) acc[i][fi] = 0.f;

        if (act8) {
            #pragma unroll 7
            for (int m = 0; m < KK; ++m) {
                float4 a0 = *(const float4*)&Hs[m * 516 + l08];
                float4 a1 = *(const float4*)&Hs[m * 516 + l08 + 4];
                float4 w0 = *(const float4*)&Ws[m * 68 + g * 8];
                float4 w1 = *(const float4*)&Ws[m * 68 + g * 8 + 4];
                float h[8] = {a0.x, a0.y, a0.z, a0.w, a1.x, a1.y, a1.z, a1.w};
                float w[8] = {w0.x, w0.y, w0.z, w0.w, w1.x, w1.y, w1.z, w1.w};
                #pragma unroll
                for (int i = 0; i < 8; i++)
                    #pragma unroll
                    for (int fi = 0; fi < 8; fi++) acc[i][fi] += h[i] * w[fi];
            }
        }
        __syncwarp();   // orders reads before in-place writes (same-warp readers)
        if (act8) {
            #pragma unroll
            for (int fi = 0; fi < 8; fi++) {
                int j = g * 8 + fi;
                if (j < KK) {
                    float4 v0, v1;
                    v0.x = fmaxf(acc[0][fi] + b2r[fi], 0.f);
                    v0.y = fmaxf(acc[1][fi] + b2r[fi], 0.f);
                    v0.z = fmaxf(acc[2][fi] + b2r[fi], 0.f);
                    v0.w = fmaxf(acc[3][fi] + b2r[fi], 0.f);
                    v1.x = fmaxf(acc[4][fi] + b2r[fi], 0.f);
                    v1.y = fmaxf(acc[5][fi] + b2r[fi], 0.f);
                    v1.z = fmaxf(acc[6][fi] + b2r[fi], 0.f);
                    v1.w = fmaxf(acc[7][fi] + b2r[fi], 0.f);
                    *(float4*)&Hs[j * 516 + l08]     = v0;
                    *(float4*)&Hs[j * 516 + l08 + 4] = v1;
                }
            }
        }
    }
    __syncthreads();   // W2 reads done before Phase C restages Ws

    // ---------- Phase C: 5-row tiles, capacity 320/pass (one balanced pass) ----------
    const int base0 = lt * 5;

    for (int r = 0; r < 32; ++r) {
        {
            const float4* src = (const float4*)(g_W3S + r * 4096);
            #pragma unroll 2
            for (int idx = t; idx < 1024; idx += 512) {
                int jj = idx >> 4, q = idx & 15;
                *(float4*)&Ws[jj * 68 + q * 4] = src[idx];
            }
        }
        __syncthreads();

        float Sp[8], Ap[8];
        #pragma unroll
        for (int fi = 0; fi < 8; fi++) { Sp[fi] = 0.f; Ap[fi] = 0.f; }

        for (int b = base0; b < Lm; b += 320) {   // virtually always 1 iteration
            float acc[5][8];
            #pragma unroll
            for (int i = 0; i < 5; i++)
                #pragma unroll
                for (int fi = 0; fi < 8; fi++) acc[i][fi] = 0.f;

            #pragma unroll 8
            for (int j = 0; j < 64; ++j) {        // j=63 ones-row adds b3*log2e
                const float* hp = &Hs[j * 516 + b];
                float h[5];
                #pragma unroll
                for (int i = 0; i < 5; i++) h[i] = hp[i];
                float4 w0 = *(const float4*)&Ws[j * 68 + g * 8];
                float4 w1 = *(const float4*)&Ws[j * 68 + g * 8 + 4];
                float w[8] = {w0.x, w0.y, w0.z, w0.w, w1.x, w1.y, w1.z, w1.w};
                #pragma unroll
                for (int i = 0; i < 5; i++)
                    #pragma unroll
                    for (int fi = 0; fi < 8; fi++) acc[i][fi] += h[i] * w[fi];
            }

            #pragma unroll
            for (int i = 0; i < 5; i++) {
                if (b + i < Lm) {                 // guard: no garbage X/H reaches sums
                    float4 x0 = *(const float4*)&Xs[(b + i) * 32 + gq4];
                    float4 x1 = *(const float4*)&Xs[(b + i) * 32 + gq4 + 4];
                    float x8[8] = {x0.x, x0.y, x0.z, x0.w, x1.x, x1.y, x1.z, x1.w};
                    #pragma unroll
                    for (int fi = 0; fi < 8; fi++) {
                        float e = exp2f(acc[i][fi]);
                        Sp[fi] += e;
                        Ap[fi] += e * x8[fi];     // d = 8*(g&3) + fi
                    }
                }
            }
        }

        #pragma unroll
        for (int fi = 0; fi < 8; fi++) {
            Sp[fi] += __shfl_xor_sync(0xffffffffu, Sp[fi], 8);
            Sp[fi] += __shfl_xor_sync(0xffffffffu, Sp[fi], 16);
            Ap[fi] += __shfl_xor_sync(0xffffffffu, Ap[fi], 8);
            Ap[fi] += __shfl_xor_sync(0xffffffffu, Ap[fi], 16);
        }
        if (lane < 8) {
            float4 s0 = {Sp[0], Sp[1], Sp[2], Sp[3]};
            float4 s1 = {Sp[4], Sp[5], Sp[6], Sp[7]};
            float4 a0 = {Ap[0], Ap[1], Ap[2], Ap[3]};
            float4 a1 = {Ap[4], Ap[5], Ap[6], Ap[7]};
            *(float4*)&R1[warp * 64 + lane * 8]     = s0;
            *(float4*)&R1[warp * 64 + lane * 8 + 4] = s1;
            *(float4*)&R2[warp * 64 + lane * 8]     = a0;
            *(float4*)&R2[warp * 64 + lane * 8 + 4] = a1;
        }
        __syncthreads();
        if (t < 64) {
            float S = 0.f, A = 0.f;
            #pragma unroll
            for (int w16 = 0; w16 < 16; w16++) {
                S += R1[w16 * 64 + t];
                A += R2[w16 * 64 + t];
            }
            int f = r * 64 + t;
            float gq = (f < FF) ? (A / S) : 0.f;
            gq += __shfl_down_sync(0xffffffffu, gq, 16);
            gq += __shfl_down_sync(0xffffffffu, gq, 8);
            gq += __shfl_down_sync(0xffffffffu, gq, 4);
            gq += __shfl_down_sync(0xffffffffu, gq, 2);
            gq += __shfl_down_sync(0xffffffffu, gq, 1);
            if (lane == 0) OS[2 * r + warp] = gq;   // k = 2r + warp
        }
        // next round's stage-sync orders Ws restage vs R reads
    }
    __syncthreads();

    if (t < KK) Og[n * KK + t] = fmaxf(OS[t] + Tb[t], 0.f);
}

extern "C" void kernel_launch(void* const* d_in, const int* in_sizes, int n_in,
                              void* d_out, int out_size) {
    const float* X  = (const float*)d_in[0];
    const float* M  = (const float*)d_in[1];
    const float* W1 = (const float*)d_in[2];
    const float* b1 = (const float*)d_in[3];
    const float* W2 = (const float*)d_in[4];
    const float* b2 = (const float*)d_in[5];
    const float* W3 = (const float*)d_in[6];
    const float* b3 = (const float*)d_in[7];
    const float* Tb = (const float*)d_in[8];
    float* Og = (float*)d_out;

    prep_w3<<<(32 * 64 * 64 + 255) / 256, 256>>>(W3, b3);

    size_t smem = (size_t)SMEM_FLOATS * sizeof(float);
    cudaFuncSetAttribute(ttcn_main, cudaFuncAttributeMaxDynamicSharedMemorySize, (int)smem);
    ttcn_main<<<NB, 512, smem>>>(X, M, W1, b1, W2, b2, Tb, Og);
}